// round 14
// baseline (speedup 1.0000x reference)
#include <cuda_runtime.h>
#include <cuda_fp16.h>
#include <cstdint>
#include <cstdio>

#define N_NODES 100000
#define N_EDGES 1000000

typedef unsigned long long ull;

// ---------------- scratch layout (floats) ----------------
#define OFF_DINV 0u
#define OFF_A1   100000u
#define OFF_H1   900000u
#define OFF_A2   7300000u
#define OFF_TEXT 20100000u
#define OFF_AB   26500000u
#define OFF_CD   39300000u
#define OFF_G    52100000u
#define OFF_H1T  52112288u
#define OFF_GH1  52116384u
#define OFF_H2T  52128672u
#define OFF_GH2  52390816u
#define OFF_W2   53177248u
#define OFF_W1P  53189536u
#define OFF_WTP  53197728u
#define OFF_POS  53205920u
#define OFF_BSUM 53306272u
#define OFF_CUR  53306528u
#define OFF_ADJ  53406528u
#define SCRATCH_SZ 55406592u

__device__ __align__(16) float g_scratch[SCRATCH_SZ];

__device__ __forceinline__ float sigm_fast(float x) {
    return __fdividef(1.0f, 1.0f + __expf(-x));
}
__device__ __forceinline__ float tanh_fast(float x) {
    return 1.0f - __fdividef(2.0f, 1.0f + __expf(2.0f * x));
}

// ---- f32x2 packed helpers ----
__device__ __forceinline__ ull pk2(float a, float b) {
    ull u;
    asm("mov.b64 %0,{%1,%2};" : "=l"(u) : "f"(a), "f"(b));
    return u;
}
__device__ __forceinline__ void up2(ull u, float& a, float& b) {
    asm("mov.b64 {%0,%1},%2;" : "=f"(a), "=f"(b) : "l"(u));
}
__device__ __forceinline__ ull fma2(ull a, ull b, ull c) {
    ull d;
    asm("fma.rn.f32x2 %0,%1,%2,%3;" : "=l"(d) : "l"(a), "l"(b), "l"(c));
    return d;
}
__device__ __forceinline__ ull dup2(float a) { return pk2(a, a); }

// ---------------- GRU precompute, fused stage A: G, H1, GH1 per token ----------------
__global__ void table_a_kernel(const float* __restrict__ embed, const float* __restrict__ w_ih,
                               const float* __restrict__ b_ih, const float* __restrict__ w_hh,
                               const float* __restrict__ b_hh, float* __restrict__ G,
                               float* __restrict__ H1, float* __restrict__ GH1) {
    __shared__ float ev[64];
    __shared__ float Gv[192];
    __shared__ float H1v[64];
    int v = blockIdx.x, t = threadIdx.x;
    if (t < 64) ev[t] = embed[v * 64 + t];
    __syncthreads();
    float acc = b_ih[t];
    const float* wg = w_ih + t * 64;
#pragma unroll 8
    for (int k = 0; k < 64; k++) acc = fmaf(ev[k], wg[k], acc);
    Gv[t] = acc;
    G[v * 192 + t] = acc;
    __syncthreads();
    if (t < 64) {
        float r = sigm_fast(Gv[t] + b_hh[t]);
        float z = sigm_fast(Gv[64 + t] + b_hh[64 + t]);
        float n = tanh_fast(Gv[128 + t] + r * b_hh[128 + t]);
        float h = (1.0f - z) * n;
        H1v[t] = h;
        H1[v * 64 + t] = h;
    }
    __syncthreads();
    float acc2 = b_hh[t];
    const float* wh = w_hh + t * 64;
#pragma unroll 8
    for (int k = 0; k < 64; k++) acc2 = fmaf(H1v[k], wh[k], acc2);
    GH1[v * 192 + t] = acc2;
}

// ---------------- GRU precompute, fused stage B: H2, GH2 per token pair ----------------
__global__ void table_b_kernel(const float* __restrict__ G, const float* __restrict__ GH1,
                               const float* __restrict__ H1, const float* __restrict__ w_hh,
                               const float* __restrict__ b_hh, float* __restrict__ H2,
                               float* __restrict__ GH2) {
    __shared__ float h2row[64];
    __shared__ float outsh[192];
    int t = threadIdx.x;
    float bh = b_hh[t];
    const float* wg = w_hh + t * 64;
    for (int q = 0; q < 8; q++) {
        int p = blockIdx.x * 8 + q;
        int v0 = p >> 6, v1 = p & 63;
        __syncthreads();
        if (t < 64) {
            float r = sigm_fast(G[v1 * 192 + t] + GH1[v0 * 192 + t]);
            float z = sigm_fast(G[v1 * 192 + 64 + t] + GH1[v0 * 192 + 64 + t]);
            float n = tanh_fast(G[v1 * 192 + 128 + t] + r * GH1[v0 * 192 + 128 + t]);
            float h = (1.0f - z) * n + z * H1[v0 * 64 + t];
            h2row[t] = h;
            H2[(size_t)p * 64 + t] = h;
        }
        __syncthreads();
        float acc = bh;
#pragma unroll 8
        for (int k = 0; k < 64; k++) acc = fmaf(h2row[k], wg[k], acc);
        outsh[t] = acc;
        __syncthreads();
        if (t < 96) {
            int g = t >> 5, l = t & 31;
            *(float2*)(GH2 + (size_t)p * 192 + 2 * t) =
                make_float2(outsh[g * 64 + l], outsh[g * 64 + 32 + l]);
        }
    }
}

__global__ void wpack_kernel(const float* __restrict__ w_hh, float* __restrict__ W2) {
    int i = blockIdx.x * blockDim.x + threadIdx.x;
    if (i >= 6144) return;
    int k = i / 96, j = i % 96, g = j >> 5, l = j & 31;
    *(float2*)(W2 + 2 * i) = make_float2(w_hh[(g * 64 + l) * 64 + k],
                                         w_hh[(g * 64 + 32 + l) * 64 + k]);
}

// ---------------- GRU main: steps 3..9, f32x2 packed, 8 nodes/warp ----------------
__global__ void __launch_bounds__(512) gru_kernel(const int* __restrict__ xtext,
                                                  const float* __restrict__ G,
                                                  const float* __restrict__ H2,
                                                  const float* __restrict__ GH2,
                                                  const float* __restrict__ W2,
                                                  const float* __restrict__ b_hh,
                                                  float* __restrict__ textout) {
    extern __shared__ ull sh[];
    ull* w2 = sh;             // [64][96]
    ull* G2 = sh + 6144;      // [64][96]
    ull* hshb = sh + 12288;   // [16 warps][8][64]

    int tid = threadIdx.x;
    const ull* W2g = (const ull*)W2;
    for (int i = tid; i < 6144; i += 512) w2[i] = W2g[i];
    for (int i = tid; i < 6144; i += 512) {
        int v = i / 96, j = i % 96, g = j >> 5, l = j & 31;
        int base = v * 192 + g * 64 + l;
        G2[i] = pk2(G[base], G[base + 32]);
    }
    __syncthreads();

    int warp = tid >> 5, lane = tid & 31;
    int nbase = (blockIdx.x * 16 + warp) * 8;
    if (nbase >= N_NODES) return;
    ull* hsh = hshb + warp * 512;

    ull bhr = pk2(b_hh[lane],       b_hh[32 + lane]);
    ull bhz = pk2(b_hh[64 + lane],  b_hh[96 + lane]);
    ull bhn = pk2(b_hh[128 + lane], b_hh[160 + lane]);

    int node = nbase + lane;
    int v2tok = 0, ptok = 0;
    ull tokpack = 0ull;
    if (lane < 8 && node < N_NODES) {
        const int* xr = xtext + (size_t)node * 10;
        int v0 = xr[0], v1 = xr[1];
        v2tok = xr[2];
        ptok = v0 * 64 + v1;
#pragma unroll
        for (int t = 3; t < 10; t++) tokpack |= (ull)xr[t] << (6 * (t - 3));
    }

    float h0[8], h1[8];
#pragma unroll
    for (int m = 0; m < 8; m++) {
        int pm = __shfl_sync(0xffffffffu, ptok, m);
        int v2 = __shfl_sync(0xffffffffu, v2tok, m);
        const ull* ghb = (const ull*)(GH2 + (size_t)pm * 192);
        float gr0, gr1, gz0, gz1, gn0, gn1;
        up2(ghb[lane], gr0, gr1);
        up2(ghb[32 + lane], gz0, gz1);
        up2(ghb[64 + lane], gn0, gn1);
        const ull* gib = G2 + v2 * 96;
        float ir0, ir1, iz0, iz1, in0, in1;
        up2(gib[lane], ir0, ir1);
        up2(gib[32 + lane], iz0, iz1);
        up2(gib[64 + lane], in0, in1);
        float hp0 = H2[(size_t)pm * 64 + lane];
        float hp1 = H2[(size_t)pm * 64 + 32 + lane];
        float r0 = sigm_fast(ir0 + gr0), r1 = sigm_fast(ir1 + gr1);
        float z0 = sigm_fast(iz0 + gz0), z1 = sigm_fast(iz1 + gz1);
        float n0 = tanh_fast(in0 + r0 * gn0), n1 = tanh_fast(in1 + r1 * gn1);
        h0[m] = (1.0f - z0) * n0 + z0 * hp0;
        h1[m] = (1.0f - z1) * n1 + z1 * hp1;
        hsh[m * 64 + lane] = dup2(h0[m]);
        hsh[m * 64 + 32 + lane] = dup2(h1[m]);
    }
    __syncwarp();

    for (int t = 0; t < 7; t++) {
        int vcur = (int)(tokpack & 63ull);
        tokpack >>= 6;
        int vm[8];
#pragma unroll
        for (int m = 0; m < 8; m++) vm[m] = __shfl_sync(0xffffffffu, vcur, m);

        ull ar[8], az[8], an[8];
#pragma unroll
        for (int m = 0; m < 8; m++) { ar[m] = bhr; az[m] = bhz; an[m] = bhn; }

        const ull* wp = w2;
#pragma unroll 4
        for (int k = 0; k < 64; k++) {
            ull wr = wp[lane];
            ull wz = wp[32 + lane];
            ull wn = wp[64 + lane];
            wp += 96;
#pragma unroll
            for (int m = 0; m < 8; m++) {
                ull hd = hsh[m * 64 + k];
                ar[m] = fma2(hd, wr, ar[m]);
                az[m] = fma2(hd, wz, az[m]);
                an[m] = fma2(hd, wn, an[m]);
            }
        }
        __syncwarp();
#pragma unroll
        for (int m = 0; m < 8; m++) {
            const ull* gib = G2 + vm[m] * 96;
            float ir0, ir1, iz0, iz1, in0, in1;
            up2(gib[lane], ir0, ir1);
            up2(gib[32 + lane], iz0, iz1);
            up2(gib[64 + lane], in0, in1);
            float hr0, hr1, hz0, hz1, hn0, hn1;
            up2(ar[m], hr0, hr1);
            up2(az[m], hz0, hz1);
            up2(an[m], hn0, hn1);
            float r0 = sigm_fast(ir0 + hr0), r1 = sigm_fast(ir1 + hr1);
            float z0 = sigm_fast(iz0 + hz0), z1 = sigm_fast(iz1 + hz1);
            float n0 = tanh_fast(in0 + r0 * hn0), n1 = tanh_fast(in1 + r1 * hn1);
            h0[m] = (1.0f - z0) * n0 + z0 * h0[m];
            h1[m] = (1.0f - z1) * n1 + z1 * h1[m];
            hsh[m * 64 + lane] = dup2(h0[m]);
            hsh[m * 64 + 32 + lane] = dup2(h1[m]);
        }
        __syncwarp();
    }

#pragma unroll
    for (int m = 0; m < 8; m++) {
        int nn = nbase + m;
        if (nn < N_NODES) {
            textout[(size_t)nn * 64 + lane] = h0[m];
            textout[(size_t)nn * 64 + 32 + lane] = h1[m];
        }
    }
}

// ---------------- degree / norm ----------------
__global__ void init_deg_kernel(float* __restrict__ deg) {
    int i = blockIdx.x * blockDim.x + threadIdx.x;
    if (i < N_NODES) deg[i] = 1.0f;
}

__global__ void count_deg_kernel(const int* __restrict__ ei, float* __restrict__ deg) {
    int e = blockIdx.x * blockDim.x + threadIdx.x;
    if (e < N_EDGES) atomicAdd(&deg[ei[N_EDGES + e]], 1.0f);
}

__global__ void rsqrt_kernel(float* __restrict__ deg) {
    int i = blockIdx.x * blockDim.x + threadIdx.x;
    if (i < N_NODES) deg[i] = rsqrtf(deg[i]);
}

// ---------------- CSR build ----------------
__global__ void scan1_kernel(const float* __restrict__ deg, int* __restrict__ pos,
                             int* __restrict__ bsum) {
    __shared__ int sd[512];
    int i = blockIdx.x * 512 + threadIdx.x;
    int v = (i < N_NODES) ? (int)deg[i] - 1 : 0;
    sd[threadIdx.x] = v;
    __syncthreads();
#pragma unroll
    for (int off = 1; off < 512; off <<= 1) {
        int t = (threadIdx.x >= off) ? sd[threadIdx.x - off] : 0;
        __syncthreads();
        sd[threadIdx.x] += t;
        __syncthreads();
    }
    if (i < N_NODES) pos[i] = sd[threadIdx.x] - v;
    if (threadIdx.x == 511) bsum[blockIdx.x] = sd[511];
}

__global__ void scan2_kernel(int* __restrict__ bsum) {
    __shared__ int sd[256];
    int t = threadIdx.x;
    int v = (t < 196) ? bsum[t] : 0;
    sd[t] = v;
    __syncthreads();
#pragma unroll
    for (int off = 1; off < 256; off <<= 1) {
        int u = (t >= off) ? sd[t - off] : 0;
        __syncthreads();
        sd[t] += u;
        __syncthreads();
    }
    if (t < 196) bsum[t] = sd[t] - v;
}

__global__ void scan3_kernel(int* __restrict__ pos, const int* __restrict__ bsum,
                             int* __restrict__ cursor) {
    int i = blockIdx.x * 512 + threadIdx.x;
    if (i < N_NODES) {
        pos[i] += bsum[blockIdx.x];
        cursor[i] = 0;
    }
}

__global__ void fill_csr_kernel(const int* __restrict__ ei, const float* __restrict__ dinv,
                                const int* __restrict__ pos, int* __restrict__ cursor,
                                int2* __restrict__ adj) {
    int e = blockIdx.x * blockDim.x + threadIdx.x;
    if (e >= N_EDGES) return;
    int s = ei[e], d = ei[N_EDGES + e];
    float w = dinv[s] * dinv[d];
    int off = atomicAdd(&cursor[d], 1);
    adj[pos[d] + off] = make_int2(s, __float_as_int(w));
}

// ---------------- GCN layer 1: gather 8-dim ----------------
__global__ void gather8_kernel(const int2* __restrict__ adj, const int* __restrict__ pos,
                               const float* __restrict__ x, const float* __restrict__ dinv,
                               float* __restrict__ a1) {
    int n = blockIdx.x * blockDim.x + threadIdx.x;
    if (n >= N_NODES) return;
    int beg = pos[n];
    int end = (n == N_NODES - 1) ? N_EDGES : pos[n + 1];
    float dd = dinv[n];
    float s2 = dd * dd;
    const float4* xn = (const float4*)(x + (size_t)n * 8);
    float4 v0 = xn[0], v1 = xn[1];
    float4 acc0 = make_float4(v0.x * s2, v0.y * s2, v0.z * s2, v0.w * s2);
    float4 acc1 = make_float4(v1.x * s2, v1.y * s2, v1.z * s2, v1.w * s2);
    for (int j = beg; j < end; j++) {
        int2 e = adj[j];
        float w = __int_as_float(e.y);
        const float4* xs = (const float4*)(x + (size_t)e.x * 8);
        float4 u0 = xs[0], u1 = xs[1];
        acc0.x = fmaf(w, u0.x, acc0.x); acc0.y = fmaf(w, u0.y, acc0.y);
        acc0.z = fmaf(w, u0.z, acc0.z); acc0.w = fmaf(w, u0.w, acc0.w);
        acc1.x = fmaf(w, u1.x, acc1.x); acc1.y = fmaf(w, u1.y, acc1.y);
        acc1.z = fmaf(w, u1.z, acc1.z); acc1.w = fmaf(w, u1.w, acc1.w);
    }
    float4* out = (float4*)(a1 + (size_t)n * 8);
    out[0] = acc0;
    out[1] = acc1;
}

// h1 = relu(a1 @ W1 + b1), 16 nodes/block
__global__ void __launch_bounds__(256) gemm8_kernel(const float* __restrict__ a1,
                                                    const float* __restrict__ W,
                                                    const float* __restrict__ bias,
                                                    float* __restrict__ h1) {
    __shared__ float Wsh[8 * 64];
    __shared__ float bsh[64];
    __shared__ float rows[16][8];
    int tid = threadIdx.x;
    for (int i = tid; i < 512; i += 256) Wsh[i] = W[i];
    if (tid < 64) bsh[tid] = bias[tid];
    int nb = blockIdx.x * 16;
    if (tid < 32) {
        ((float4*)rows)[tid] = ((const float4*)(a1 + (size_t)nb * 8))[tid];
    }
    __syncthreads();
#pragma unroll
    for (int o = tid; o < 1024; o += 256) {
        int nl = o >> 6;
        int col = o & 63;
        float acc = bsh[col];
#pragma unroll
        for (int k = 0; k < 8; k++) acc = fmaf(rows[nl][k], Wsh[k * 64 + col], acc);
        h1[(size_t)(nb + nl) * 64 + col] = fmaxf(acc, 0.0f);
    }
}

// ---------------- GCN layer 2: gather 64-dim, warp per node ----------------
__global__ void __launch_bounds__(256) gather64_kernel(const int2* __restrict__ adj,
                                                       const int* __restrict__ pos,
                                                       const float* __restrict__ h1,
                                                       const float* __restrict__ dinv,
                                                       float* __restrict__ a2) {
    int warp = threadIdx.x >> 5, lane = threadIdx.x & 31;
    int n = blockIdx.x * 8 + warp;
    if (n >= N_NODES) return;
    int beg = pos[n];
    int end = (n == N_NODES - 1) ? N_EDGES : pos[n + 1];
    float dd = dinv[n];
    float s2 = dd * dd;
    float acc0 = h1[(size_t)n * 64 + lane] * s2;
    float acc1 = h1[(size_t)n * 64 + 32 + lane] * s2;
    int cnt = end - beg;
    for (int base = 0; base < cnt; base += 32) {
        int take = cnt - base;
        if (take > 32) take = 32;
        int2 ej = (lane < take) ? adj[beg + base + lane] : make_int2(0, 0);
        int m = 0;
        for (; m + 1 < take; m += 2) {
            int s0 = __shfl_sync(0xffffffffu, ej.x, m);
            float w0 = __int_as_float(__shfl_sync(0xffffffffu, ej.y, m));
            int s1 = __shfl_sync(0xffffffffu, ej.x, m + 1);
            float w1 = __int_as_float(__shfl_sync(0xffffffffu, ej.y, m + 1));
            const float* r0 = h1 + (size_t)s0 * 64;
            const float* r1 = h1 + (size_t)s1 * 64;
            float x0 = r0[lane], x1 = r0[32 + lane];
            float y0 = r1[lane], y1 = r1[32 + lane];
            acc0 = fmaf(w0, x0, acc0);
            acc1 = fmaf(w0, x1, acc1);
            acc0 = fmaf(w1, y0, acc0);
            acc1 = fmaf(w1, y1, acc1);
        }
        if (m < take) {
            int s0 = __shfl_sync(0xffffffffu, ej.x, m);
            float w0 = __int_as_float(__shfl_sync(0xffffffffu, ej.y, m));
            const float* r0 = h1 + (size_t)s0 * 64;
            acc0 = fmaf(w0, r0[lane], acc0);
            acc1 = fmaf(w0, r0[32 + lane], acc1);
        }
    }
    a2[(size_t)n * 64 + lane] = acc0;
    a2[(size_t)n * 64 + 32 + lane] = acc1;
}

// ---------------- pack pair-MLP weights to k-major [64][128], both at once ----------------
__global__ void wpack128_kernel(const float* __restrict__ W1, const float* __restrict__ WT,
                                float* __restrict__ out1, float* __restrict__ outT) {
    int i = blockIdx.x * blockDim.x + threadIdx.x;
    if (i >= 16384) return;
    const float* W = (i < 8192) ? W1 : WT;
    float* out = (i < 8192) ? out1 : outT;
    int ii = i & 8191;
    int k = ii >> 7, j = ii & 127;
    out[ii] = (j < 64) ? W[j * 128 + k] : W[(j - 64) * 128 + 64 + k];
}

// ---- store float4 as 8 fp16 (uint2) ----
__device__ __forceinline__ void st_half4x2(__half* dst, float4 a, float4 b) {
    __half2 h0 = __floats2half2_rn(a.x, a.y);
    __half2 h1 = __floats2half2_rn(a.z, a.w);
    __half2 h2 = __floats2half2_rn(b.x, b.y);
    __half2 h3 = __floats2half2_rn(b.z, b.w);
    uint4 u;
    u.x = *(unsigned*)&h0; u.y = *(unsigned*)&h1;
    u.z = *(unsigned*)&h2; u.w = *(unsigned*)&h3;
    *(uint4*)dst = u;
}

// ---------------- fused conv2 GEMM + AB pair-GEMM (h2 stays in smem), fp16 out ----------------
__global__ void __launch_bounds__(256) conv2_ab_kernel(const float* __restrict__ a2,
                                                       const float* __restrict__ Wc,
                                                       const float* __restrict__ b2,
                                                       const float* __restrict__ W1P,
                                                       const float* __restrict__ b1,
                                                       __half* __restrict__ AB) {
    extern __shared__ __align__(16) float dyn[];
    float* Wcsh = dyn;            // 4096
    float* W1sh = dyn + 4096;     // 8192
    float* rows = dyn + 12288;    // 1024
    float* h2sh = dyn + 13312;    // 1024
    int tid = threadIdx.x;
    {
        const float4* s1 = (const float4*)Wc;
        float4* d1 = (float4*)Wcsh;
        for (int i = tid; i < 1024; i += 256) d1[i] = s1[i];
        const float4* s2 = (const float4*)W1P;
        float4* d2 = (float4*)W1sh;
        for (int i = tid; i < 2048; i += 256) d2[i] = s2[i];
    }
    int nb = blockIdx.x * 16;
    {
        const float4* in4 = (const float4*)(a2 + (size_t)nb * 64);
        ((float4*)rows)[tid] = in4[tid];
    }
    __syncthreads();
    {
        int nl = tid >> 4;
        int colb = (tid & 15) * 4;
        ull a01 = pk2(b2[colb], b2[colb + 1]);
        ull a23 = pk2(b2[colb + 2], b2[colb + 3]);
        const float* r = rows + nl * 64;
#pragma unroll
        for (int k = 0; k < 64; k++) {
            ull bb = dup2(r[k]);
            const ull* wp = (const ull*)&Wcsh[k * 64 + colb];
            a01 = fma2(bb, wp[0], a01);
            a23 = fma2(bb, wp[1], a23);
        }
        float4 h;
        up2(a01, h.x, h.y);
        up2(a23, h.z, h.w);
        h.x = fmaxf(h.x, 0.0f); h.y = fmaxf(h.y, 0.0f);
        h.z = fmaxf(h.z, 0.0f); h.w = fmaxf(h.w, 0.0f);
        *(float4*)&h2sh[nl * 64 + colb] = h;
    }
    __syncthreads();
    // phase 2: AB = h2 @ W1P (+ lin1_b on first half), 2 nodes/thread, 8 cols/thread
    int nl = tid >> 4;                 // 0..15: node pair index? -> use 16 threads/node-pair? keep 2 nodes/thread, 8 cols
    int colb = (tid & 15) * 8;
    int n0 = nb + nl;
    float c[8];
#pragma unroll
    for (int j = 0; j < 8; j++) c[j] = (colb + j < 64) ? b1[colb + j] : 0.0f;
    ull x01 = pk2(c[0], c[1]), x23 = pk2(c[2], c[3]);
    ull x45 = pk2(c[4], c[5]), x67 = pk2(c[6], c[7]);
    const float* r0 = h2sh + nl * 64;
#pragma unroll
    for (int k = 0; k < 64; k++) {
        ull u0 = dup2(r0[k]);
        const ull* wp = (const ull*)&W1sh[k * 128 + colb];
        x01 = fma2(u0, wp[0], x01);
        x23 = fma2(u0, wp[1], x23);
        x45 = fma2(u0, wp[2], x45);
        x67 = fma2(u0, wp[3], x67);
    }
    float4 oa, ob;
    up2(x01, oa.x, oa.y); up2(x23, oa.z, oa.w);
    up2(x45, ob.x, ob.y); up2(x67, ob.z, ob.w);
    st_half4x2(AB + (size_t)n0 * 128 + colb, oa, ob);
}

// ---------------- [N,64] @ [64,128] GEMM, fp16 out (for CD) ----------------
__global__ void __launch_bounds__(256) gemm128_kernel(const float* __restrict__ in,
                                                      const float* __restrict__ W,
                                                      const float* __restrict__ bias,
                                                      __half* __restrict__ out) {
    __shared__ __align__(16) float Wsh[64 * 128];
    __shared__ __align__(16) float rows[16 * 64];
    int tid = threadIdx.x;
    const float4* W4 = (const float4*)W;
    float4* Wsh4 = (float4*)Wsh;
    for (int i = tid; i < 2048; i += 256) Wsh4[i] = W4[i];
    int nb = blockIdx.x * 16;
    {
        const float4* in4 = (const float4*)(in + (size_t)nb * 64);
        ((float4*)rows)[tid] = in4[tid];
    }
    __syncthreads();
    int nl = tid >> 4;
    int colb = (tid & 15) * 8;
    int n0 = nb + nl;
    float c[8];
#pragma unroll
    for (int j = 0; j < 8; j++) c[j] = (colb + j < 64) ? bias[colb + j] : 0.0f;
    ull x01 = pk2(c[0], c[1]), x23 = pk2(c[2], c[3]);
    ull x45 = pk2(c[4], c[5]), x67 = pk2(c[6], c[7]);
    const float* r0 = rows + nl * 64;
#pragma unroll
    for (int k = 0; k < 64; k++) {
        ull u0 = dup2(r0[k]);
        const ull* wp = (const ull*)&Wsh[k * 128 + colb];
        x01 = fma2(u0, wp[0], x01);
        x23 = fma2(u0, wp[1], x23);
        x45 = fma2(u0, wp[2], x45);
        x67 = fma2(u0, wp[3], x67);
    }
    float4 oa, ob;
    up2(x01, oa.x, oa.y); up2(x23, oa.z, oa.w);
    up2(x45, ob.x, ob.y); up2(x67, ob.z, ob.w);
    st_half4x2(out + (size_t)n0 * 128 + colb, oa, ob);
}

// ---- dot of 8 relu(a+b) terms from fp16-packed loads ----
__device__ __forceinline__ float dot8_relu(uint4 ua, uint4 ub, const float* w) {
    const __half2* pa = (const __half2*)&ua;
    const __half2* pb = (const __half2*)&ub;
    float acc = 0.0f;
#pragma unroll
    for (int i = 0; i < 4; i++) {
        float2 fa = __half22float2(pa[i]);
        float2 fb = __half22float2(pb[i]);
        acc = fmaf(w[2 * i],     fmaxf(fa.x + fb.x, 0.0f), acc);
        acc = fmaf(w[2 * i + 1], fmaxf(fa.y + fb.y, 0.0f), acc);
    }
    return acc;
}

// ---------------- final per-edge kernel: 8 lanes/edge, fp16 tables, logit-diff ----------------
__global__ void __launch_bounds__(256) edge_final_kernel(const int* __restrict__ ei,
                                                         const __half* __restrict__ AB,
                                                         const __half* __restrict__ CD,
                                                         const float* __restrict__ Wf,
                                                         const float* __restrict__ bf,
                                                         float* __restrict__ out) {
    int lane = threadIdx.x & 31;
    int q = lane & 7;
    int g = lane >> 3;
    int gw = (blockIdx.x * blockDim.x + threadIdx.x) >> 5;
    int nw = (gridDim.x * blockDim.x) >> 5;

    float wp[8], wt[8];
#pragma unroll
    for (int j = 0; j < 8; j++) {
        int d = q * 8 + j;
        wp[j] = Wf[128 + d] - Wf[d];
        wt[j] = Wf[192 + d] - Wf[64 + d];
    }
    float bd = bf[1] - bf[0];

    for (int e4 = gw * 4; e4 < N_EDGES; e4 += nw * 4) {
        int e = e4 + g;
        int s = ei[e], t = ei[N_EDGES + e];
        uint4 ua = ((const uint4*)(AB + (size_t)s * 128))[q];
        uint4 ub = ((const uint4*)(AB + (size_t)t * 128 + 64))[q];
        uint4 uc = ((const uint4*)(CD + (size_t)s * 128))[q];
        uint4 ud = ((const uint4*)(CD + (size_t)t * 128 + 64))[q];

        float acc = dot8_relu(ua, ub, wp) + dot8_relu(uc, ud, wt);

        acc += __shfl_xor_sync(0xffffffffu, acc, 4);
        acc += __shfl_xor_sync(0xffffffffu, acc, 2);
        acc += __shfl_xor_sync(0xffffffffu, acc, 1);

        if (q == 0) {
            float dlt = acc + bd;
            float lt = fmaxf(dlt, 0.0f) + log1pf(__expf(-fabsf(dlt)));
            *(float2*)(out + 2 * (size_t)e) = make_float2(-lt, dlt - lt);
        }
    }
}

// ---------------- launch ----------------
extern "C" void kernel_launch(void* const* d_in, const int* in_sizes, int n_in,
                              void* d_out, int out_size) {
    const float* x        = (const float*)d_in[0];
    const int*   ei       = (const int*)d_in[1];
    const int*   xtext    = (const int*)d_in[2];
    const float* conv1_w  = (const float*)d_in[3];
    const float* conv1_b  = (const float*)d_in[4];
    const float* conv2_w  = (const float*)d_in[5];
    const float* conv2_b  = (const float*)d_in[6];
    const float* embed    = (const float*)d_in[7];
    const float* gru_w_ih = (const float*)d_in[8];
    const float* gru_w_hh = (const float*)d_in[9];
    const float* gru_b_ih = (const float*)d_in[10];
    const float* gru_b_hh = (const float*)d_in[11];
    const float* lin1_w   = (const float*)d_in[12];
    const float* lin1_b   = (const float*)d_in[13];
    const float* lin_text_w = (const float*)d_in[14];
    const float* lin_text_b = (const float*)d_in[15];
    const float* lin_final_w = (const float*)d_in[16];
    const float* lin_final_b = (const float*)d_in[17];
    float* out = (float*)d_out;

    float* S = nullptr;
    cudaGetSymbolAddress((void**)&S, g_scratch);
    float* dinv = S + OFF_DINV;
    float* a1   = S + OFF_A1;
    float* h1   = S + OFF_H1;
    float* a2   = S + OFF_A2;
    float* text = S + OFF_TEXT;
    __half* ABh = (__half*)(S + OFF_AB);
    __half* CDh = (__half*)(S + OFF_CD);
    float* G    = S + OFF_G;
    float* H1T  = S + OFF_H1T;
    float* GH1  = S + OFF_GH1;
    float* H2T  = S + OFF_H2T;
    float* GH2  = S + OFF_GH2;
    float* W2   = S + OFF_W2;
    float* W1P  = S + OFF_W1P;
    float* WTP  = S + OFF_WTP;
    int*   pos  = (int*)(S + OFF_POS);
    int*   bsum = (int*)(S + OFF_BSUM);
    int*   cur  = (int*)(S + OFF_CUR);
    int2*  adj  = (int2*)(S + OFF_ADJ);

    (void)cudaFuncSetAttribute(gru_kernel, cudaFuncAttributeMaxDynamicSharedMemorySize, 163840);
    (void)cudaFuncSetAttribute(conv2_ab_kernel, cudaFuncAttributeMaxDynamicSharedMemorySize, 57344);

    // GRU chain first: gru at launch index 3 (profiled slot)
    table_a_kernel<<<64, 192>>>(embed, gru_w_ih, gru_b_ih, gru_w_hh, gru_b_hh, G, H1T, GH1); // 0
    wpack_kernel<<<24, 256>>>(gru_w_hh, W2);                                                  // 1
    table_b_kernel<<<512, 192>>>(G, GH1, H1T, gru_w_hh, gru_b_hh, H2T, GH2);                  // 2
    gru_kernel<<<782, 512, 163840>>>(xtext, G, H2T, GH2, W2, gru_b_hh, text);                 // 3 <-- profiled

    // degree / norm / CSR
    init_deg_kernel<<<391, 256>>>(dinv);
    count_deg_kernel<<<3907, 256>>>(ei, dinv);
    scan1_kernel<<<196, 512>>>(dinv, pos, bsum);
    scan2_kernel<<<1, 256>>>(bsum);
    scan3_kernel<<<196, 512>>>(pos, bsum, cur);
    rsqrt_kernel<<<391, 256>>>(dinv);
    fill_csr_kernel<<<3907, 256>>>(ei, dinv, pos, cur, adj);
    wpack128_kernel<<<64, 256>>>(lin1_w, lin_text_w, W1P, WTP);

    // GCN layer 1 (gather)
    gather8_kernel<<<391, 256>>>(adj, pos, x, dinv, a1);
    gemm8_kernel<<<6250, 256>>>(a1, conv1_w, conv1_b, h1);

    // GCN layer 2 (gather) + fused conv2-GEMM + AB pair-GEMM (fp16 out)
    gather64_kernel<<<12500, 256>>>(adj, pos, h1, dinv, a2);
    conv2_ab_kernel<<<6250, 256, 57344>>>(a2, conv2_w, conv2_b, W1P, lin1_b, ABh);

    // CD pair-GEMM (fp16 out)
    gemm128_kernel<<<6250, 256>>>(text, WTP, lin_text_b, CDh);

    // per-edge final + log_softmax (fp16 tables, logit-diff form)
    edge_final_kernel<<<8192, 256>>>(ei, ABh, CDh, lin_final_w, lin_final_b, out);
}

// round 16
// speedup vs baseline: 1.3671x; 1.3671x over previous
#include <cuda_runtime.h>
#include <cuda_fp16.h>
#include <cstdint>
#include <cstdio>

#define N_NODES 100000
#define N_EDGES 1000000

typedef unsigned long long ull;

// ---------------- scratch layout (floats) ----------------
#define OFF_DINV 0u
#define OFF_A1   100000u
#define OFF_H1   900000u
#define OFF_A2   7300000u
#define OFF_TEXT 20100000u
#define OFF_AB   26500000u
#define OFF_CD   39300000u
#define OFF_G    52100000u
#define OFF_H1T  52112288u
#define OFF_GH1  52116384u
#define OFF_H2T  52128672u
#define OFF_GH2  52390816u
#define OFF_W2   53177248u
#define OFF_W1P  53189536u
#define OFF_WTP  53197728u
#define OFF_POS  53205920u
#define OFF_BSUM 53306272u
#define OFF_CUR  53306528u
#define OFF_ADJ  53406528u
#define SCRATCH_SZ 55406592u

__device__ __align__(16) float g_scratch[SCRATCH_SZ];

__device__ __forceinline__ float sigm_fast(float x) {
    return __fdividef(1.0f, 1.0f + __expf(-x));
}
__device__ __forceinline__ float tanh_fast(float x) {
    return 1.0f - __fdividef(2.0f, 1.0f + __expf(2.0f * x));
}

// ---- f32x2 packed helpers ----
__device__ __forceinline__ ull pk2(float a, float b) {
    ull u;
    asm("mov.b64 %0,{%1,%2};" : "=l"(u) : "f"(a), "f"(b));
    return u;
}
__device__ __forceinline__ void up2(ull u, float& a, float& b) {
    asm("mov.b64 {%0,%1},%2;" : "=f"(a), "=f"(b) : "l"(u));
}
__device__ __forceinline__ ull fma2(ull a, ull b, ull c) {
    ull d;
    asm("fma.rn.f32x2 %0,%1,%2,%3;" : "=l"(d) : "l"(a), "l"(b), "l"(c));
    return d;
}
__device__ __forceinline__ ull dup2(float a) { return pk2(a, a); }

// ---------------- GRU precompute, fused stage A: G, H1, GH1 per token ----------------
__global__ void table_a_kernel(const float* __restrict__ embed, const float* __restrict__ w_ih,
                               const float* __restrict__ b_ih, const float* __restrict__ w_hh,
                               const float* __restrict__ b_hh, float* __restrict__ G,
                               float* __restrict__ H1, float* __restrict__ GH1) {
    __shared__ float ev[64];
    __shared__ float Gv[192];
    __shared__ float H1v[64];
    int v = blockIdx.x, t = threadIdx.x;
    if (t < 64) ev[t] = embed[v * 64 + t];
    __syncthreads();
    float acc = b_ih[t];
    const float* wg = w_ih + t * 64;
#pragma unroll 8
    for (int k = 0; k < 64; k++) acc = fmaf(ev[k], wg[k], acc);
    Gv[t] = acc;
    G[v * 192 + t] = acc;
    __syncthreads();
    if (t < 64) {
        float r = sigm_fast(Gv[t] + b_hh[t]);
        float z = sigm_fast(Gv[64 + t] + b_hh[64 + t]);
        float n = tanh_fast(Gv[128 + t] + r * b_hh[128 + t]);
        float h = (1.0f - z) * n;
        H1v[t] = h;
        H1[v * 64 + t] = h;
    }
    __syncthreads();
    float acc2 = b_hh[t];
    const float* wh = w_hh + t * 64;
#pragma unroll 8
    for (int k = 0; k < 64; k++) acc2 = fmaf(H1v[k], wh[k], acc2);
    GH1[v * 192 + t] = acc2;
}

// ---------------- GRU precompute, fused stage B: H2, GH2 per token pair ----------------
__global__ void table_b_kernel(const float* __restrict__ G, const float* __restrict__ GH1,
                               const float* __restrict__ H1, const float* __restrict__ w_hh,
                               const float* __restrict__ b_hh, float* __restrict__ H2,
                               float* __restrict__ GH2) {
    __shared__ float h2row[64];
    __shared__ float outsh[192];
    int t = threadIdx.x;
    float bh = b_hh[t];
    const float* wg = w_hh + t * 64;
    for (int q = 0; q < 8; q++) {
        int p = blockIdx.x * 8 + q;
        int v0 = p >> 6, v1 = p & 63;
        __syncthreads();
        if (t < 64) {
            float r = sigm_fast(G[v1 * 192 + t] + GH1[v0 * 192 + t]);
            float z = sigm_fast(G[v1 * 192 + 64 + t] + GH1[v0 * 192 + 64 + t]);
            float n = tanh_fast(G[v1 * 192 + 128 + t] + r * GH1[v0 * 192 + 128 + t]);
            float h = (1.0f - z) * n + z * H1[v0 * 64 + t];
            h2row[t] = h;
            H2[(size_t)p * 64 + t] = h;
        }
        __syncthreads();
        float acc = bh;
#pragma unroll 8
        for (int k = 0; k < 64; k++) acc = fmaf(h2row[k], wg[k], acc);
        outsh[t] = acc;
        __syncthreads();
        if (t < 96) {
            int g = t >> 5, l = t & 31;
            *(float2*)(GH2 + (size_t)p * 192 + 2 * t) =
                make_float2(outsh[g * 64 + l], outsh[g * 64 + 32 + l]);
        }
    }
}

__global__ void wpack_kernel(const float* __restrict__ w_hh, float* __restrict__ W2) {
    int i = blockIdx.x * blockDim.x + threadIdx.x;
    if (i >= 6144) return;
    int k = i / 96, j = i % 96, g = j >> 5, l = j & 31;
    *(float2*)(W2 + 2 * i) = make_float2(w_hh[(g * 64 + l) * 64 + k],
                                         w_hh[(g * 64 + 32 + l) * 64 + k]);
}

// ---------------- GRU main: steps 3..9, f32x2 packed, 8 nodes/warp, fp32 h in smem --------
__global__ void __launch_bounds__(512) gru_kernel(const int* __restrict__ xtext,
                                                  const float* __restrict__ G,
                                                  const float* __restrict__ H2,
                                                  const float* __restrict__ GH2,
                                                  const float* __restrict__ W2,
                                                  const float* __restrict__ b_hh,
                                                  float* __restrict__ textout) {
    extern __shared__ ull sh[];
    ull* w2 = sh;                        // [64][96] packed weight pairs (48 KB)
    ull* G2 = sh + 6144;                 // [64][96] packed input gates (48 KB)
    float* hshb = (float*)(sh + 12288);  // [16 warps][8][64] fp32 h (32 KB)

    int tid = threadIdx.x;
    const ull* W2g = (const ull*)W2;
    for (int i = tid; i < 6144; i += 512) w2[i] = W2g[i];
    for (int i = tid; i < 6144; i += 512) {
        int v = i / 96, j = i % 96, g = j >> 5, l = j & 31;
        int base = v * 192 + g * 64 + l;
        G2[i] = pk2(G[base], G[base + 32]);
    }
    __syncthreads();

    int warp = tid >> 5, lane = tid & 31;
    int nbase = (blockIdx.x * 16 + warp) * 8;
    if (nbase >= N_NODES) return;
    float* hsh = hshb + warp * 512;

    ull bhr = pk2(b_hh[lane],       b_hh[32 + lane]);
    ull bhz = pk2(b_hh[64 + lane],  b_hh[96 + lane]);
    ull bhn = pk2(b_hh[128 + lane], b_hh[160 + lane]);

    int node = nbase + lane;
    int v2tok = 0, ptok = 0;
    ull tokpack = 0ull;
    if (lane < 8 && node < N_NODES) {
        const int* xr = xtext + (size_t)node * 10;
        int v0 = xr[0], v1 = xr[1];
        v2tok = xr[2];
        ptok = v0 * 64 + v1;
#pragma unroll
        for (int t = 3; t < 10; t++) tokpack |= (ull)xr[t] << (6 * (t - 3));
    }

    float h0[8], h1[8];
#pragma unroll
    for (int m = 0; m < 8; m++) {
        int pm = __shfl_sync(0xffffffffu, ptok, m);
        int v2 = __shfl_sync(0xffffffffu, v2tok, m);
        const ull* ghb = (const ull*)(GH2 + (size_t)pm * 192);
        float gr0, gr1, gz0, gz1, gn0, gn1;
        up2(ghb[lane], gr0, gr1);
        up2(ghb[32 + lane], gz0, gz1);
        up2(ghb[64 + lane], gn0, gn1);
        const ull* gib = G2 + v2 * 96;
        float ir0, ir1, iz0, iz1, in0, in1;
        up2(gib[lane], ir0, ir1);
        up2(gib[32 + lane], iz0, iz1);
        up2(gib[64 + lane], in0, in1);
        float hp0 = H2[(size_t)pm * 64 + lane];
        float hp1 = H2[(size_t)pm * 64 + 32 + lane];
        float r0 = sigm_fast(ir0 + gr0), r1 = sigm_fast(ir1 + gr1);
        float z0 = sigm_fast(iz0 + gz0), z1 = sigm_fast(iz1 + gz1);
        float n0 = tanh_fast(in0 + r0 * gn0), n1 = tanh_fast(in1 + r1 * gn1);
        h0[m] = (1.0f - z0) * n0 + z0 * hp0;
        h1[m] = (1.0f - z1) * n1 + z1 * hp1;
        hsh[m * 64 + lane] = h0[m];
        hsh[m * 64 + 32 + lane] = h1[m];
    }
    __syncwarp();

    for (int t = 0; t < 7; t++) {
        int vcur = (int)(tokpack & 63ull);
        tokpack >>= 6;
        int vm[8];
#pragma unroll
        for (int m = 0; m < 8; m++) vm[m] = __shfl_sync(0xffffffffu, vcur, m);

        ull ar[8], az[8], an[8];
#pragma unroll
        for (int m = 0; m < 8; m++) { ar[m] = bhr; az[m] = bhz; an[m] = bhn; }

        const ull* wp = w2;
#pragma unroll 4
        for (int k = 0; k < 64; k++) {
            ull wr = wp[lane];
            ull wz = wp[32 + lane];
            ull wn = wp[64 + lane];
            wp += 96;
#pragma unroll
            for (int m = 0; m < 8; m++) {
                ull hd = dup2(hsh[m * 64 + k]);   // LDS.32 broadcast + reg-dup
                ar[m] = fma2(hd, wr, ar[m]);
                az[m] = fma2(hd, wz, az[m]);
                an[m] = fma2(hd, wn, an[m]);
            }
        }
        __syncwarp();
#pragma unroll
        for (int m = 0; m < 8; m++) {
            const ull* gib = G2 + vm[m] * 96;
            float ir0, ir1, iz0, iz1, in0, in1;
            up2(gib[lane], ir0, ir1);
            up2(gib[32 + lane], iz0, iz1);
            up2(gib[64 + lane], in0, in1);
            float hr0, hr1, hz0, hz1, hn0, hn1;
            up2(ar[m], hr0, hr1);
            up2(az[m], hz0, hz1);
            up2(an[m], hn0, hn1);
            float r0 = sigm_fast(ir0 + hr0), r1 = sigm_fast(ir1 + hr1);
            float z0 = sigm_fast(iz0 + hz0), z1 = sigm_fast(iz1 + hz1);
            float n0 = tanh_fast(in0 + r0 * hn0), n1 = tanh_fast(in1 + r1 * hn1);
            h0[m] = (1.0f - z0) * n0 + z0 * h0[m];
            h1[m] = (1.0f - z1) * n1 + z1 * h1[m];
            hsh[m * 64 + lane] = h0[m];
            hsh[m * 64 + 32 + lane] = h1[m];
        }
        __syncwarp();
    }

#pragma unroll
    for (int m = 0; m < 8; m++) {
        int nn = nbase + m;
        if (nn < N_NODES) {
            textout[(size_t)nn * 64 + lane] = h0[m];
            textout[(size_t)nn * 64 + 32 + lane] = h1[m];
        }
    }
}

// ---------------- degree / norm ----------------
__global__ void init_deg_kernel(float* __restrict__ deg) {
    int i = blockIdx.x * blockDim.x + threadIdx.x;
    if (i < N_NODES) deg[i] = 1.0f;
}

__global__ void count_deg_kernel(const int* __restrict__ ei, float* __restrict__ deg) {
    int e = blockIdx.x * blockDim.x + threadIdx.x;
    if (e < N_EDGES) atomicAdd(&deg[ei[N_EDGES + e]], 1.0f);
}

__global__ void rsqrt_kernel(float* __restrict__ deg) {
    int i = blockIdx.x * blockDim.x + threadIdx.x;
    if (i < N_NODES) deg[i] = rsqrtf(deg[i]);
}

// ---------------- CSR build ----------------
__global__ void scan1_kernel(const float* __restrict__ deg, int* __restrict__ pos,
                             int* __restrict__ bsum) {
    __shared__ int sd[512];
    int i = blockIdx.x * 512 + threadIdx.x;
    int v = (i < N_NODES) ? (int)deg[i] - 1 : 0;
    sd[threadIdx.x] = v;
    __syncthreads();
#pragma unroll
    for (int off = 1; off < 512; off <<= 1) {
        int t = (threadIdx.x >= off) ? sd[threadIdx.x - off] : 0;
        __syncthreads();
        sd[threadIdx.x] += t;
        __syncthreads();
    }
    if (i < N_NODES) pos[i] = sd[threadIdx.x] - v;
    if (threadIdx.x == 511) bsum[blockIdx.x] = sd[511];
}

__global__ void scan2_kernel(int* __restrict__ bsum) {
    __shared__ int sd[256];
    int t = threadIdx.x;
    int v = (t < 196) ? bsum[t] : 0;
    sd[t] = v;
    __syncthreads();
#pragma unroll
    for (int off = 1; off < 256; off <<= 1) {
        int u = (t >= off) ? sd[t - off] : 0;
        __syncthreads();
        sd[t] += u;
        __syncthreads();
    }
    if (t < 196) bsum[t] = sd[t] - v;
}

__global__ void scan3_kernel(int* __restrict__ pos, const int* __restrict__ bsum,
                             int* __restrict__ cursor) {
    int i = blockIdx.x * 512 + threadIdx.x;
    if (i < N_NODES) {
        pos[i] += bsum[blockIdx.x];
        cursor[i] = 0;
    }
}

__global__ void fill_csr_kernel(const int* __restrict__ ei, const float* __restrict__ dinv,
                                const int* __restrict__ pos, int* __restrict__ cursor,
                                int2* __restrict__ adj) {
    int e = blockIdx.x * blockDim.x + threadIdx.x;
    if (e >= N_EDGES) return;
    int s = ei[e], d = ei[N_EDGES + e];
    float w = dinv[s] * dinv[d];
    int off = atomicAdd(&cursor[d], 1);
    adj[pos[d] + off] = make_int2(s, __float_as_int(w));
}

// ---------------- GCN layer 1: gather 8-dim ----------------
__global__ void gather8_kernel(const int2* __restrict__ adj, const int* __restrict__ pos,
                               const float* __restrict__ x, const float* __restrict__ dinv,
                               float* __restrict__ a1) {
    int n = blockIdx.x * blockDim.x + threadIdx.x;
    if (n >= N_NODES) return;
    int beg = pos[n];
    int end = (n == N_NODES - 1) ? N_EDGES : pos[n + 1];
    float dd = dinv[n];
    float s2 = dd * dd;
    const float4* xn = (const float4*)(x + (size_t)n * 8);
    float4 v0 = xn[0], v1 = xn[1];
    float4 acc0 = make_float4(v0.x * s2, v0.y * s2, v0.z * s2, v0.w * s2);
    float4 acc1 = make_float4(v1.x * s2, v1.y * s2, v1.z * s2, v1.w * s2);
    for (int j = beg; j < end; j++) {
        int2 e = adj[j];
        float w = __int_as_float(e.y);
        const float4* xs = (const float4*)(x + (size_t)e.x * 8);
        float4 u0 = xs[0], u1 = xs[1];
        acc0.x = fmaf(w, u0.x, acc0.x); acc0.y = fmaf(w, u0.y, acc0.y);
        acc0.z = fmaf(w, u0.z, acc0.z); acc0.w = fmaf(w, u0.w, acc0.w);
        acc1.x = fmaf(w, u1.x, acc1.x); acc1.y = fmaf(w, u1.y, acc1.y);
        acc1.z = fmaf(w, u1.z, acc1.z); acc1.w = fmaf(w, u1.w, acc1.w);
    }
    float4* out = (float4*)(a1 + (size_t)n * 8);
    out[0] = acc0;
    out[1] = acc1;
}

// h1 = relu(a1 @ W1 + b1), 16 nodes/block
__global__ void __launch_bounds__(256) gemm8_kernel(const float* __restrict__ a1,
                                                    const float* __restrict__ W,
                                                    const float* __restrict__ bias,
                                                    float* __restrict__ h1) {
    __shared__ float Wsh[8 * 64];
    __shared__ float bsh[64];
    __shared__ float rows[16][8];
    int tid = threadIdx.x;
    for (int i = tid; i < 512; i += 256) Wsh[i] = W[i];
    if (tid < 64) bsh[tid] = bias[tid];
    int nb = blockIdx.x * 16;
    if (tid < 32) {
        ((float4*)rows)[tid] = ((const float4*)(a1 + (size_t)nb * 8))[tid];
    }
    __syncthreads();
#pragma unroll
    for (int o = tid; o < 1024; o += 256) {
        int nl = o >> 6;
        int col = o & 63;
        float acc = bsh[col];
#pragma unroll
        for (int k = 0; k < 8; k++) acc = fmaf(rows[nl][k], Wsh[k * 64 + col], acc);
        h1[(size_t)(nb + nl) * 64 + col] = fmaxf(acc, 0.0f);
    }
}

// ---------------- GCN layer 2: gather 64-dim, warp per node ----------------
__global__ void __launch_bounds__(256) gather64_kernel(const int2* __restrict__ adj,
                                                       const int* __restrict__ pos,
                                                       const float* __restrict__ h1,
                                                       const float* __restrict__ dinv,
                                                       float* __restrict__ a2) {
    int warp = threadIdx.x >> 5, lane = threadIdx.x & 31;
    int n = blockIdx.x * 8 + warp;
    if (n >= N_NODES) return;
    int beg = pos[n];
    int end = (n == N_NODES - 1) ? N_EDGES : pos[n + 1];
    float dd = dinv[n];
    float s2 = dd * dd;
    float acc0 = h1[(size_t)n * 64 + lane] * s2;
    float acc1 = h1[(size_t)n * 64 + 32 + lane] * s2;
    int cnt = end - beg;
    for (int base = 0; base < cnt; base += 32) {
        int take = cnt - base;
        if (take > 32) take = 32;
        int2 ej = (lane < take) ? adj[beg + base + lane] : make_int2(0, 0);
        int m = 0;
        for (; m + 1 < take; m += 2) {
            int s0 = __shfl_sync(0xffffffffu, ej.x, m);
            float w0 = __int_as_float(__shfl_sync(0xffffffffu, ej.y, m));
            int s1 = __shfl_sync(0xffffffffu, ej.x, m + 1);
            float w1 = __int_as_float(__shfl_sync(0xffffffffu, ej.y, m + 1));
            const float* r0 = h1 + (size_t)s0 * 64;
            const float* r1 = h1 + (size_t)s1 * 64;
            float x0 = r0[lane], x1 = r0[32 + lane];
            float y0 = r1[lane], y1 = r1[32 + lane];
            acc0 = fmaf(w0, x0, acc0);
            acc1 = fmaf(w0, x1, acc1);
            acc0 = fmaf(w1, y0, acc0);
            acc1 = fmaf(w1, y1, acc1);
        }
        if (m < take) {
            int s0 = __shfl_sync(0xffffffffu, ej.x, m);
            float w0 = __int_as_float(__shfl_sync(0xffffffffu, ej.y, m));
            const float* r0 = h1 + (size_t)s0 * 64;
            acc0 = fmaf(w0, r0[lane], acc0);
            acc1 = fmaf(w0, r0[32 + lane], acc1);
        }
    }
    a2[(size_t)n * 64 + lane] = acc0;
    a2[(size_t)n * 64 + 32 + lane] = acc1;
}

// ---------------- pack pair-MLP weights to k-major [64][128], both at once ----------------
__global__ void wpack128_kernel(const float* __restrict__ W1, const float* __restrict__ WT,
                                float* __restrict__ out1, float* __restrict__ outT) {
    int i = blockIdx.x * blockDim.x + threadIdx.x;
    if (i >= 16384) return;
    const float* W = (i < 8192) ? W1 : WT;
    float* out = (i < 8192) ? out1 : outT;
    int ii = i & 8191;
    int k = ii >> 7, j = ii & 127;
    out[ii] = (j < 64) ? W[j * 128 + k] : W[(j - 64) * 128 + 64 + k];
}

// ---- store 4 fp32 (as 2 packed ulls) to 4 fp16 ----
__device__ __forceinline__ void st_half4(__half* dst, ull a01, ull a23) {
    float f0, f1, f2, f3;
    up2(a01, f0, f1);
    up2(a23, f2, f3);
    __half2 h0 = __floats2half2_rn(f0, f1);
    __half2 h1 = __floats2half2_rn(f2, f3);
    uint2 u;
    u.x = *(unsigned*)&h0;
    u.y = *(unsigned*)&h1;
    *(uint2*)dst = u;
}

// ---------------- fused conv2 GEMM + AB pair-GEMM, 32 nodes/block, fp16 out -------------
// dyn smem: Wc[4096] | W1[8192] | rows[2048] | h2[2048] = 16384 floats = 64 KB
__global__ void __launch_bounds__(256) conv2_ab_kernel(const float* __restrict__ a2,
                                                       const float* __restrict__ Wc,
                                                       const float* __restrict__ b2,
                                                       const float* __restrict__ W1P,
                                                       const float* __restrict__ b1,
                                                       __half* __restrict__ AB) {
    extern __shared__ __align__(16) float dyn[];
    float* Wcsh = dyn;            // 4096
    float* W1sh = dyn + 4096;     // 8192
    float* rows = dyn + 12288;    // 2048
    float* h2sh = dyn + 14336;    // 2048
    int tid = threadIdx.x;
    {
        const float4* s1 = (const float4*)Wc;
        float4* d1 = (float4*)Wcsh;
        for (int i = tid; i < 1024; i += 256) d1[i] = s1[i];
        const float4* s2 = (const float4*)W1P;
        float4* d2 = (float4*)W1sh;
        for (int i = tid; i < 2048; i += 256) d2[i] = s2[i];
    }
    int nb = blockIdx.x * 32;
    {
        const float4* in4 = (const float4*)(a2 + (size_t)nb * 64);
        float4* r4 = (float4*)rows;
        for (int i = tid; i < 512; i += 256) r4[i] = in4[i];
    }
    __syncthreads();
    // phase 1: h2 = relu(a2 @ Wc + b2), 8 threads/node, 8 cols/thread
    {
        int nl = tid >> 3;
        int colb = (tid & 7) * 8;
        ull a01 = pk2(b2[colb],     b2[colb + 1]);
        ull a23 = pk2(b2[colb + 2], b2[colb + 3]);
        ull a45 = pk2(b2[colb + 4], b2[colb + 5]);
        ull a67 = pk2(b2[colb + 6], b2[colb + 7]);
        const float* r = rows + nl * 64;
#pragma unroll
        for (int k = 0; k < 64; k++) {
            ull bb = dup2(r[k]);
            const ull* wp = (const ull*)&Wcsh[k * 64 + colb];
            a01 = fma2(bb, wp[0], a01);
            a23 = fma2(bb, wp[1], a23);
            a45 = fma2(bb, wp[2], a45);
            a67 = fma2(bb, wp[3], a67);
        }
        float f0, f1, f2, f3, f4, f5, f6, f7;
        up2(a01, f0, f1); up2(a23, f2, f3);
        up2(a45, f4, f5); up2(a67, f6, f7);
        float4 ha = make_float4(fmaxf(f0, 0.f), fmaxf(f1, 0.f), fmaxf(f2, 0.f), fmaxf(f3, 0.f));
        float4 hb = make_float4(fmaxf(f4, 0.f), fmaxf(f5, 0.f), fmaxf(f6, 0.f), fmaxf(f7, 0.f));
        *(float4*)&h2sh[nl * 64 + colb] = ha;
        *(float4*)&h2sh[nl * 64 + colb + 4] = hb;
    }
    __syncthreads();
    // phase 2: AB = h2 @ W1P (+bias first half), 4 nodes/thread, 4 cols
    int g = tid >> 5;               // 0..7 -> nodes g*4 .. g*4+3
    int colb = (tid & 31) * 4;
    float c0, c1, c2, c3;
    if (colb < 64) { c0 = b1[colb]; c1 = b1[colb+1]; c2 = b1[colb+2]; c3 = b1[colb+3]; }
    else           { c0 = c1 = c2 = c3 = 0.0f; }
    ull x01[4], x23[4];
#pragma unroll
    for (int j = 0; j < 4; j++) { x01[j] = pk2(c0, c1); x23[j] = pk2(c2, c3); }
    const float* rbase = h2sh + g * 256;
#pragma unroll
    for (int k = 0; k < 64; k++) {
        const ull* wp = (const ull*)&W1sh[k * 128 + colb];
        ull w0 = wp[0], w1 = wp[1];
#pragma unroll
        for (int j = 0; j < 4; j++) {
            ull u = dup2(rbase[j * 64 + k]);
            x01[j] = fma2(u, w0, x01[j]);
            x23[j] = fma2(u, w1, x23[j]);
        }
    }
#pragma unroll
    for (int j = 0; j < 4; j++) {
        int n0 = nb + g * 4 + j;
        st_half4(AB + (size_t)n0 * 128 + colb, x01[j], x23[j]);
    }
}

// ---------------- [N,64] @ [64,128] GEMM, 32 nodes/block, fp16 out (for CD) -------------
__global__ void __launch_bounds__(256) gemm128_kernel(const float* __restrict__ in,
                                                      const float* __restrict__ W,
                                                      const float* __restrict__ bias,
                                                      __half* __restrict__ out) {
    __shared__ __align__(16) float Wsh[64 * 128];
    __shared__ __align__(16) float rows[32 * 64];
    int tid = threadIdx.x;
    const float4* W4 = (const float4*)W;
    float4* Wsh4 = (float4*)Wsh;
    for (int i = tid; i < 2048; i += 256) Wsh4[i] = W4[i];
    int nb = blockIdx.x * 32;
    {
        const float4* in4 = (const float4*)(in + (size_t)nb * 64);
        float4* r4 = (float4*)rows;
        for (int i = tid; i < 512; i += 256) r4[i] = in4[i];
    }
    __syncthreads();
    int g = tid >> 5;
    int colb = (tid & 31) * 4;
    float c0, c1, c2, c3;
    if (colb < 64) { c0 = bias[colb]; c1 = bias[colb+1]; c2 = bias[colb+2]; c3 = bias[colb+3]; }
    else           { c0 = c1 = c2 = c3 = 0.0f; }
    ull x01[4], x23[4];
#pragma unroll
    for (int j = 0; j < 4; j++) { x01[j] = pk2(c0, c1); x23[j] = pk2(c2, c3); }
    const float* rbase = rows + g * 256;
#pragma unroll
    for (int k = 0; k < 64; k++) {
        const ull* wp = (const ull*)&Wsh[k * 128 + colb];
        ull w0 = wp[0], w1 = wp[1];
#pragma unroll
        for (int j = 0; j < 4; j++) {
            ull u = dup2(rbase[j * 64 + k]);
            x01[j] = fma2(u, w0, x01[j]);
            x23[j] = fma2(u, w1, x23[j]);
        }
    }
#pragma unroll
    for (int j = 0; j < 4; j++) {
        int n0 = nb + g * 4 + j;
        st_half4(out + (size_t)n0 * 128 + colb, x01[j], x23[j]);
    }
}

// ---- dot of 8 relu(a+b) terms from fp16-packed loads ----
__device__ __forceinline__ float dot8_relu(uint4 ua, uint4 ub, const float* w) {
    const __half2* pa = (const __half2*)&ua;
    const __half2* pb = (const __half2*)&ub;
    float acc = 0.0f;
#pragma unroll
    for (int i = 0; i < 4; i++) {
        float2 fa = __half22float2(pa[i]);
        float2 fb = __half22float2(pb[i]);
        acc = fmaf(w[2 * i],     fmaxf(fa.x + fb.x, 0.0f), acc);
        acc = fmaf(w[2 * i + 1], fmaxf(fa.y + fb.y, 0.0f), acc);
    }
    return acc;
}

// ---------------- final per-edge kernel: 8 lanes/edge, fp16 tables, logit-diff ----------------
__global__ void __launch_bounds__(256) edge_final_kernel(const int* __restrict__ ei,
                                                         const __half* __restrict__ AB,
                                                         const __half* __restrict__ CD,
                                                         const float* __restrict__ Wf,
                                                         const float* __restrict__ bf,
                                                         float* __restrict__ out) {
    int lane = threadIdx.x & 31;
    int q = lane & 7;
    int g = lane >> 3;
    int gw = (blockIdx.x * blockDim.x + threadIdx.x) >> 5;
    int nw = (gridDim.x * blockDim.x) >> 5;

    float wp[8], wt[8];
#pragma unroll
    for (int j = 0; j < 8; j++) {
        int d = q * 8 + j;
        wp[j] = Wf[128 + d] - Wf[d];
        wt[j] = Wf[192 + d] - Wf[64 + d];
    }
    float bd = bf[1] - bf[0];

    for (int e4 = gw * 4; e4 < N_EDGES; e4 += nw * 4) {
        int e = e4 + g;
        int s = ei[e], t = ei[N_EDGES + e];
        uint4 ua = ((const uint4*)(AB + (size_t)s * 128))[q];
        uint4 ub = ((const uint4*)(AB + (size_t)t * 128 + 64))[q];
        uint4 uc = ((const uint4*)(CD + (size_t)s * 128))[q];
        uint4 ud = ((const uint4*)(CD + (size_t)t * 128 + 64))[q];

        float acc = dot8_relu(ua, ub, wp) + dot8_relu(uc, ud, wt);

        acc += __shfl_xor_sync(0xffffffffu, acc, 4);
        acc += __shfl_xor_sync(0xffffffffu, acc, 2);
        acc += __shfl_xor_sync(0xffffffffu, acc, 1);

        if (q == 0) {
            float dlt = acc + bd;
            float lt = fmaxf(dlt, 0.0f) + log1pf(__expf(-fabsf(dlt)));
            *(float2*)(out + 2 * (size_t)e) = make_float2(-lt, dlt - lt);
        }
    }
}

// ---------------- launch ----------------
extern "C" void kernel_launch(void* const* d_in, const int* in_sizes, int n_in,
                              void* d_out, int out_size) {
    const float* x        = (const float*)d_in[0];
    const int*   ei       = (const int*)d_in[1];
    const int*   xtext    = (const int*)d_in[2];
    const float* conv1_w  = (const float*)d_in[3];
    const float* conv1_b  = (const float*)d_in[4];
    const float* conv2_w  = (const float*)d_in[5];
    const float* conv2_b  = (const float*)d_in[6];
    const float* embed    = (const float*)d_in[7];
    const float* gru_w_ih = (const float*)d_in[8];
    const float* gru_w_hh = (const float*)d_in[9];
    const float* gru_b_ih = (const float*)d_in[10];
    const float* gru_b_hh = (const float*)d_in[11];
    const float* lin1_w   = (const float*)d_in[12];
    const float* lin1_b   = (const float*)d_in[13];
    const float* lin_text_w = (const float*)d_in[14];
    const float* lin_text_b = (const float*)d_in[15];
    const float* lin_final_w = (const float*)d_in[16];
    const float* lin_final_b = (const float*)d_in[17];
    float* out = (float*)d_out;

    float* S = nullptr;
    cudaGetSymbolAddress((void**)&S, g_scratch);
    float* dinv = S + OFF_DINV;
    float* a1   = S + OFF_A1;
    float* h1   = S + OFF_H1;
    float* a2   = S + OFF_A2;
    float* text = S + OFF_TEXT;
    __half* ABh = (__half*)(S + OFF_AB);
    __half* CDh = (__half*)(S + OFF_CD);
    float* G    = S + OFF_G;
    float* H1T  = S + OFF_H1T;
    float* GH1  = S + OFF_GH1;
    float* H2T  = S + OFF_H2T;
    float* GH2  = S + OFF_GH2;
    float* W2   = S + OFF_W2;
    float* W1P  = S + OFF_W1P;
    float* WTP  = S + OFF_WTP;
    int*   pos  = (int*)(S + OFF_POS);
    int*   bsum = (int*)(S + OFF_BSUM);
    int*   cur  = (int*)(S + OFF_CUR);
    int2*  adj  = (int2*)(S + OFF_ADJ);

    (void)cudaFuncSetAttribute(gru_kernel, cudaFuncAttributeMaxDynamicSharedMemorySize, 131072);
    (void)cudaFuncSetAttribute(conv2_ab_kernel, cudaFuncAttributeMaxDynamicSharedMemorySize, 65536);

    // GRU chain first: gru at launch index 3 (profiled slot)
    table_a_kernel<<<64, 192>>>(embed, gru_w_ih, gru_b_ih, gru_w_hh, gru_b_hh, G, H1T, GH1); // 0
    wpack_kernel<<<24, 256>>>(gru_w_hh, W2);                                                  // 1
    table_b_kernel<<<512, 192>>>(G, GH1, H1T, gru_w_hh, gru_b_hh, H2T, GH2);                  // 2
    gru_kernel<<<782, 512, 131072>>>(xtext, G, H2T, GH2, W2, gru_b_hh, text);                 // 3 <-- profiled

    // degree / norm / CSR
    init_deg_kernel<<<391, 256>>>(dinv);
    count_deg_kernel<<<3907, 256>>>(ei, dinv);
    scan1_kernel<<<196, 512>>>(dinv, pos, bsum);
    scan2_kernel<<<1, 256>>>(bsum);
    scan3_kernel<<<196, 512>>>(pos, bsum, cur);
    rsqrt_kernel<<<391, 256>>>(dinv);
    fill_csr_kernel<<<3907, 256>>>(ei, dinv, pos, cur, adj);
    wpack128_kernel<<<64, 256>>>(lin1_w, lin_text_w, W1P, WTP);

    // GCN layer 1 (gather)
    gather8_kernel<<<391, 256>>>(adj, pos, x, dinv, a1);
    gemm8_kernel<<<6250, 256>>>(a1, conv1_w, conv1_b, h1);

    // GCN layer 2 (gather) + fused conv2-GEMM + AB pair-GEMM (fp16 out)
    gather64_kernel<<<12500, 256>>>(adj, pos, h1, dinv, a2);
    conv2_ab_kernel<<<3125, 256, 65536>>>(a2, conv2_w, conv2_b, W1P, lin1_b, ABh);

    // CD pair-GEMM (fp16 out)
    gemm128_kernel<<<3125, 256>>>(text, WTP, lin_text_b, CDh);

    // per-edge final + log_softmax (fp16 tables, logit-diff form)
    edge_final_kernel<<<8192, 256>>>(ei, ABh, CDh, lin_final_w, lin_final_b, out);
}